// round 1
// baseline (speedup 1.0000x reference)
#include <cuda_runtime.h>

// ---------------------------------------------------------------------------
// HourlyWaterQualityPredictor — fused ConvLSTM(12 steps) + decoder, fp32.
// One CTA = NB batch elements, 512 threads (64 per batch element).
// Thread (bi, hp, r): batch bi, hidden-channel pair {2hp, 2hp+1}, image row r.
// Conv weights live in smem permuted as [k(9)][ic(35)][oc(128)].
// Per-batch smem "in" buffer [35ch][16pix] also doubles as the decoder's
// z-vector (spatial = channels 3..34, hour-feature appended at 560..591).
// ---------------------------------------------------------------------------

#define NB    8
#define NTHR  512
#define ICH   35           // 3 input + 32 hidden channels
#define INS   592          // per-batch floats: 35*16 + 32 (hour feature)
#define WCNT  (9 * 35 * 128)  // 40320 conv weights

__device__ __forceinline__ float sigf(float v) {
    return __fdividef(1.0f, 1.0f + __expf(-v));
}
__device__ __forceinline__ float tanh_fast(float v) {
    v = fminf(fmaxf(v, -15.0f), 15.0f);
    float e = __expf(2.0f * v);
    return __fdividef(e - 1.0f, e + 1.0f);
}

#define GETC(v4, idx) ((idx) == 0 ? (v4).x : (idx) == 1 ? (v4).y : (idx) == 2 ? (v4).z : (v4).w)

extern __shared__ float smem[];

__global__ __launch_bounds__(NTHR, 1)
void wq_fused_kernel(const float* __restrict__ x,      const float* __restrict__ hour,
                     const float* __restrict__ conv_w, const float* __restrict__ conv_b,
                     const float* __restrict__ he_w1,  const float* __restrict__ he_b1,
                     const float* __restrict__ he_w2,  const float* __restrict__ he_b2,
                     const float* __restrict__ d_w1,   const float* __restrict__ d_b1,
                     const float* __restrict__ d_w2,   const float* __restrict__ d_b2,
                     const float* __restrict__ d_w3,   const float* __restrict__ d_b3,
                     float* __restrict__ out, int B)
{
    float* w_s    = smem;            // [9][35][128]
    float* b_s    = w_s + WCNT;      // [128]
    float* in_all = b_s + 128;       // [NB][INS]

    const int tid = threadIdx.x;
    const int bi  = tid >> 6;        // batch within CTA
    const int tib = tid & 63;        // thread within batch
    const int hp  = tib >> 2;        // hidden-channel pair 0..15
    const int r   = tib & 3;         // image row 0..3
    const int b0  = blockIdx.x * NB;
    const int b   = b0 + bi;
    const bool valid = (b < B);
    const int  bld   = valid ? b : (B - 1);

    // ---- stage conv weights into smem, permuted [k][ic][oc] ----
    for (int s = tid; s < WCNT; s += NTHR) {
        int oc  = s / 315;
        int rem = s - oc * 315;
        int ic  = rem / 9;
        int k   = rem - ic * 9;
        w_s[(k * 35 + ic) * 128 + oc] = conv_w[s];
    }
    for (int s = tid; s < 128; s += NTHR) b_s[s] = conv_b[s];

    // ---- zero state, then load x_0 ----
    for (int s = tid; s < NB * INS; s += NTHR) in_all[s] = 0.0f;
    __syncthreads();
    for (int s = tid; s < NB * 48; s += NTHR) {
        int bb = s / 48, cp = s - bb * 48;
        int gb = b0 + bb;
        if (gb < B) in_all[bb * INS + cp] = x[gb * 576 + cp];
    }
    __syncthreads();

    float* inb = in_all + bi * INS;
    const float* wb0 = w_s + 2 * hp;   // + ic*128 + k*4480 + gate*32 below

    float cst[2][4];
    #pragma unroll
    for (int h = 0; h < 2; h++)
        #pragma unroll
        for (int p = 0; p < 4; p++) cst[h][p] = 0.0f;

    // ---------------------- 12-step ConvLSTM recurrence ----------------------
    #pragma unroll 1
    for (int t = 0; t < 12; ++t) {
        float aI[2][4], aF[2][4], aO[2][4], aG[2][4];
        #pragma unroll
        for (int h = 0; h < 2; h++) {
            float bI = b_s[      2 * hp + h];
            float bF = b_s[32  + 2 * hp + h];
            float bO = b_s[64  + 2 * hp + h];
            float bG = b_s[96  + 2 * hp + h];
            #pragma unroll
            for (int p = 0; p < 4; p++) {
                aI[h][p] = bI; aF[h][p] = bF; aO[h][p] = bO; aG[h][p] = bG;
            }
        }

        #pragma unroll 1
        for (int ic = 0; ic < ICH; ++ic) {
            const float* rowbase = inb + ic * 16;
            float4 vm = make_float4(0.f, 0.f, 0.f, 0.f);
            float4 vp = make_float4(0.f, 0.f, 0.f, 0.f);
            if (r > 0) vm = *reinterpret_cast<const float4*>(rowbase + (r - 1) * 4);
            float4 v0 = *reinterpret_cast<const float4*>(rowbase + r * 4);
            if (r < 3) vp = *reinterpret_cast<const float4*>(rowbase + (r + 1) * 4);

            const float* wic = wb0 + ic * 128;
            #pragma unroll
            for (int k = 0; k < 9; ++k) {
                const int dy = k / 3 - 1;
                const int dx = (k % 3) - 1;
                float4 rw = (dy == -1) ? vm : ((dy == 0) ? v0 : vp);
                const float* wp2 = wic + k * 4480;   // k*(35*128)
                float2 wi = *reinterpret_cast<const float2*>(wp2);
                float2 wf = *reinterpret_cast<const float2*>(wp2 + 32);
                float2 wo = *reinterpret_cast<const float2*>(wp2 + 64);
                float2 wg = *reinterpret_cast<const float2*>(wp2 + 96);
                #pragma unroll
                for (int p = 0; p < 4; ++p) {
                    const int sx = p + dx;
                    if (sx >= 0 && sx < 4) {
                        float v = GETC(rw, sx);
                        aI[0][p] += wi.x * v; aI[1][p] += wi.y * v;
                        aF[0][p] += wf.x * v; aF[1][p] += wf.y * v;
                        aO[0][p] += wo.x * v; aO[1][p] += wo.y * v;
                        aG[0][p] += wg.x * v; aG[1][p] += wg.y * v;
                    }
                }
            }
        }

        // LSTM cell update (registers only)
        float hn[2][4];
        #pragma unroll
        for (int h = 0; h < 2; h++)
            #pragma unroll
            for (int p = 0; p < 4; p++) {
                float ig = sigf(aI[h][p]);
                float fg = sigf(aF[h][p]);
                float og = sigf(aO[h][p]);
                float gg = tanh_fast(aG[h][p]);
                float cn = fg * cst[h][p] + ig * gg;
                cst[h][p] = cn;
                hn[h][p]  = og * tanh_fast(cn);
            }

        __syncthreads();   // everyone done reading in_s for this step
        #pragma unroll
        for (int h = 0; h < 2; h++)
            #pragma unroll
            for (int p = 0; p < 4; p++)
                inb[(3 + 2 * hp + h) * 16 + r * 4 + p] = hn[h][p];

        if (t < 11) {
            for (int s = tid; s < NB * 48; s += NTHR) {
                int bb = s / 48, cp = s - bb * 48;
                int gb = b0 + bb;
                if (gb < B) in_all[bb * INS + cp] = x[gb * 576 + (t + 1) * 48 + cp];
            }
        }
        __syncthreads();
    }

    // ------------------------------ decoder ------------------------------
    // hour embedding -> z[512..543] (stored at inb[560..591]; z[i] = inb[48+i])
    if (tib < 32) {
        float hv  = hour[bld];
        float acc = he_b2[tib];
        #pragma unroll
        for (int k2 = 0; k2 < 16; ++k2) {
            float tt = fmaxf(hv * he_w1[k2] + he_b1[k2], 0.0f);
            acc += tt * he_w2[k2 * 32 + tib];
        }
        inb[560 + tib] = acc;
    }
    __syncthreads();

    // L1: 544 -> 256, each thread computes 4 outputs
    float a1[4];
    {
        const int j0 = tib * 4;
        a1[0] = d_b1[j0]; a1[1] = d_b1[j0 + 1]; a1[2] = d_b1[j0 + 2]; a1[3] = d_b1[j0 + 3];
        const float* zz = inb + 48;
        #pragma unroll 4
        for (int i = 0; i < 544; ++i) {
            float zi = zz[i];
            float4 w = *reinterpret_cast<const float4*>(d_w1 + i * 256 + j0);
            a1[0] += zi * w.x; a1[1] += zi * w.y; a1[2] += zi * w.z; a1[3] += zi * w.w;
        }
        #pragma unroll
        for (int q = 0; q < 4; q++) a1[q] = fmaxf(a1[q], 0.0f);
    }
    __syncthreads();   // all z reads done
    {
        const int j0 = tib * 4;
        inb[j0] = a1[0]; inb[j0 + 1] = a1[1]; inb[j0 + 2] = a1[2]; inb[j0 + 3] = a1[3];
    }
    __syncthreads();

    // L2: 256 -> 128, each thread computes 2 outputs; writes to [256..384)
    {
        const int j0 = tib * 2;
        float a2x = d_b2[j0], a2y = d_b2[j0 + 1];
        #pragma unroll 4
        for (int i = 0; i < 256; ++i) {
            float zi = inb[i];
            float2 w = *reinterpret_cast<const float2*>(d_w2 + i * 128 + j0);
            a2x += zi * w.x; a2y += zi * w.y;
        }
        inb[256 + j0]     = fmaxf(a2x, 0.0f);   // disjoint from read region [0..256)
        inb[256 + j0 + 1] = fmaxf(a2y, 0.0f);
    }
    __syncthreads();

    // L3: 128 -> 30 + sigmoid
    if (tib < 30 && valid) {
        float a3 = d_b3[tib];
        #pragma unroll 4
        for (int i = 0; i < 128; ++i)
            a3 += inb[256 + i] * d_w3[i * 30 + tib];
        out[b * 30 + tib] = sigf(a3);
    }
}

extern "C" void kernel_launch(void* const* d_in, const int* in_sizes, int n_in,
                              void* d_out, int out_size)
{
    const float* x      = (const float*)d_in[0];
    const float* hour   = (const float*)d_in[1];
    const float* conv_w = (const float*)d_in[2];
    const float* conv_b = (const float*)d_in[3];
    const float* he_w1  = (const float*)d_in[4];
    const float* he_b1  = (const float*)d_in[5];
    const float* he_w2  = (const float*)d_in[6];
    const float* he_b2  = (const float*)d_in[7];
    const float* d_w1   = (const float*)d_in[8];
    const float* d_b1   = (const float*)d_in[9];
    const float* d_w2   = (const float*)d_in[10];
    const float* d_b2   = (const float*)d_in[11];
    const float* d_w3   = (const float*)d_in[12];
    const float* d_b3   = (const float*)d_in[13];

    const int B    = in_sizes[0] / 576;          // 12*3*4*4
    const int grid = (B + NB - 1) / NB;
    const size_t sm = (size_t)(WCNT + 128 + NB * INS) * sizeof(float);  // 180,736 B

    cudaFuncSetAttribute(wq_fused_kernel,
                         cudaFuncAttributeMaxDynamicSharedMemorySize, (int)sm);

    wq_fused_kernel<<<grid, NTHR, sm>>>(x, hour, conv_w, conv_b,
                                        he_w1, he_b1, he_w2, he_b2,
                                        d_w1, d_b1, d_w2, d_b2, d_w3, d_b3,
                                        (float*)d_out, B);
}

// round 2
// speedup vs baseline: 1.0591x; 1.0591x over previous
#include <cuda_runtime.h>

// ---------------------------------------------------------------------------
// HourlyWaterQualityPredictor — fused ConvLSTM(12 steps) + decoder, fp32.
// R2: inner conv loop uses packed fma.rn.f32x2 (2 output channels per FFMA2).
// One CTA = NB batch elements, 512 threads (64 per batch element).
// Thread (bi, hp, r): batch bi, hidden-channel pair {2hp, 2hp+1}, image row r.
// Conv weights live in smem permuted as [k(9)][ic(35)][oc(128)].
// ---------------------------------------------------------------------------

#define NB    8
#define NTHR  512
#define ICH   35              // 3 input + 32 hidden channels
#define INS   592             // per-batch floats: 35*16 + 32 (hour feature)
#define WCNT  (9 * 35 * 128)  // 40320 conv weights

typedef unsigned long long ull;

__device__ __forceinline__ ull fma2(ull a, ull b, ull c) {
    ull d;
    asm("fma.rn.f32x2 %0, %1, %2, %3;" : "=l"(d) : "l"(a), "l"(b), "l"(c));
    return d;
}
__device__ __forceinline__ ull bcast2(float v) {
    ull d;
    asm("mov.b64 %0, {%1, %1};" : "=l"(d) : "f"(v));
    return d;
}
__device__ __forceinline__ float2 unpack2(ull v) {
    float2 r;
    asm("mov.b64 {%0, %1}, %2;" : "=f"(r.x), "=f"(r.y) : "l"(v));
    return r;
}

__device__ __forceinline__ float sigf(float v) {
    return __fdividef(1.0f, 1.0f + __expf(-v));
}
__device__ __forceinline__ float tanh_fast(float v) {
    v = fminf(fmaxf(v, -15.0f), 15.0f);
    float e = __expf(2.0f * v);
    return __fdividef(e - 1.0f, e + 1.0f);
}

extern __shared__ float smem[];

__global__ __launch_bounds__(NTHR, 1)
void wq_fused_kernel(const float* __restrict__ x,      const float* __restrict__ hour,
                     const float* __restrict__ conv_w, const float* __restrict__ conv_b,
                     const float* __restrict__ he_w1,  const float* __restrict__ he_b1,
                     const float* __restrict__ he_w2,  const float* __restrict__ he_b2,
                     const float* __restrict__ d_w1,   const float* __restrict__ d_b1,
                     const float* __restrict__ d_w2,   const float* __restrict__ d_b2,
                     const float* __restrict__ d_w3,   const float* __restrict__ d_b3,
                     float* __restrict__ out, int B)
{
    float* w_s    = smem;            // [9][35][128]
    float* b_s    = w_s + WCNT;      // [128]
    float* in_all = b_s + 128;       // [NB][INS]

    const int tid = threadIdx.x;
    const int bi  = tid >> 6;        // batch within CTA
    const int tib = tid & 63;        // thread within batch
    const int hp  = tib >> 2;        // hidden-channel pair 0..15
    const int r   = tib & 3;         // image row 0..3
    const int b0  = blockIdx.x * NB;
    const int b   = b0 + bi;
    const bool valid = (b < B);
    const int  bld   = valid ? b : (B - 1);

    // ---- stage conv weights into smem, permuted [k][ic][oc] ----
    for (int s = tid; s < WCNT; s += NTHR) {
        int oc  = s / 315;
        int rem = s - oc * 315;
        int ic  = rem / 9;
        int k   = rem - ic * 9;
        w_s[(k * 35 + ic) * 128 + oc] = conv_w[s];
    }
    for (int s = tid; s < 128; s += NTHR) b_s[s] = conv_b[s];

    // ---- zero state, then load x_0 ----
    for (int s = tid; s < NB * INS; s += NTHR) in_all[s] = 0.0f;
    __syncthreads();
    for (int s = tid; s < NB * 48; s += NTHR) {
        int bb = s / 48, cp = s - bb * 48;
        int gb = b0 + bb;
        if (gb < B) in_all[bb * INS + cp] = x[gb * 576 + cp];
    }
    __syncthreads();

    float* inb = in_all + bi * INS;
    const float* wb0 = w_s + 2 * hp;   // + ic*128 + k*4480 + gate*32 below

    ull cst2[4];                       // packed c-state: 2 channels x 4 pixels
    #pragma unroll
    for (int p = 0; p < 4; p++) cst2[p] = 0ULL;

    // packed biases (channels 2hp, 2hp+1 are adjacent -> single 8B smem read)
    const ull bI2 = *reinterpret_cast<const ull*>(b_s +       2 * hp);
    const ull bF2 = *reinterpret_cast<const ull*>(b_s + 32  + 2 * hp);
    const ull bO2 = *reinterpret_cast<const ull*>(b_s + 64  + 2 * hp);
    const ull bG2 = *reinterpret_cast<const ull*>(b_s + 96  + 2 * hp);

    // ---------------------- 12-step ConvLSTM recurrence ----------------------
    #pragma unroll 1
    for (int t = 0; t < 12; ++t) {
        ull aI[4], aF[4], aO[4], aG[4];
        #pragma unroll
        for (int p = 0; p < 4; p++) { aI[p] = bI2; aF[p] = bF2; aO[p] = bO2; aG[p] = bG2; }

        #pragma unroll 1
        for (int ic = 0; ic < ICH; ++ic) {
            const float* rowbase = inb + ic * 16;
            float4 vm = make_float4(0.f, 0.f, 0.f, 0.f);
            float4 vp = make_float4(0.f, 0.f, 0.f, 0.f);
            if (r > 0) vm = *reinterpret_cast<const float4*>(rowbase + (r - 1) * 4);
            float4 v0 = *reinterpret_cast<const float4*>(rowbase + r * 4);
            if (r < 3) vp = *reinterpret_cast<const float4*>(rowbase + (r + 1) * 4);

            // broadcast-pack each row value once; reused across 9 taps x 4 gates
            ull vvm[4], vv0[4], vvp[4];
            vvm[0] = bcast2(vm.x); vvm[1] = bcast2(vm.y); vvm[2] = bcast2(vm.z); vvm[3] = bcast2(vm.w);
            vv0[0] = bcast2(v0.x); vv0[1] = bcast2(v0.y); vv0[2] = bcast2(v0.z); vv0[3] = bcast2(v0.w);
            vvp[0] = bcast2(vp.x); vvp[1] = bcast2(vp.y); vvp[2] = bcast2(vp.z); vvp[3] = bcast2(vp.w);

            const float* wic = wb0 + ic * 128;
            #pragma unroll
            for (int k = 0; k < 9; ++k) {
                const int dy = k / 3 - 1;
                const int dx = (k % 3) - 1;
                const float* wp2 = wic + k * 4480;   // k*(35*128)
                ull wi2 = *reinterpret_cast<const ull*>(wp2);
                ull wf2 = *reinterpret_cast<const ull*>(wp2 + 32);
                ull wo2 = *reinterpret_cast<const ull*>(wp2 + 64);
                ull wg2 = *reinterpret_cast<const ull*>(wp2 + 96);
                #pragma unroll
                for (int p = 0; p < 4; ++p) {
                    const int sx = p + dx;
                    if (sx >= 0 && sx < 4) {
                        ull vv = (dy == -1) ? vvm[sx] : ((dy == 0) ? vv0[sx] : vvp[sx]);
                        aI[p] = fma2(wi2, vv, aI[p]);
                        aF[p] = fma2(wf2, vv, aF[p]);
                        aO[p] = fma2(wo2, vv, aO[p]);
                        aG[p] = fma2(wg2, vv, aG[p]);
                    }
                }
            }
        }

        // LSTM cell update (registers only)
        float hn[2][4];
        #pragma unroll
        for (int p = 0; p < 4; p++) {
            float2 vi = unpack2(aI[p]);
            float2 vf = unpack2(aF[p]);
            float2 vo = unpack2(aO[p]);
            float2 vg = unpack2(aG[p]);
            float2 cprev = unpack2(cst2[p]);

            float c0 = sigf(vf.x) * cprev.x + sigf(vi.x) * tanh_fast(vg.x);
            float c1 = sigf(vf.y) * cprev.y + sigf(vi.y) * tanh_fast(vg.y);
            hn[0][p] = sigf(vo.x) * tanh_fast(c0);
            hn[1][p] = sigf(vo.y) * tanh_fast(c1);

            ull cn;
            asm("mov.b64 %0, {%1, %2};" : "=l"(cn) : "f"(c0), "f"(c1));
            cst2[p] = cn;
        }

        __syncthreads();   // everyone done reading in_s for this step
        #pragma unroll
        for (int h = 0; h < 2; h++)
            #pragma unroll
            for (int p = 0; p < 4; p++)
                inb[(3 + 2 * hp + h) * 16 + r * 4 + p] = hn[h][p];

        if (t < 11) {
            for (int s = tid; s < NB * 48; s += NTHR) {
                int bb = s / 48, cp = s - bb * 48;
                int gb = b0 + bb;
                if (gb < B) in_all[bb * INS + cp] = x[gb * 576 + (t + 1) * 48 + cp];
            }
        }
        __syncthreads();
    }

    // ------------------------------ decoder ------------------------------
    // hour embedding -> z[512..543] (stored at inb[560..591]; z[i] = inb[48+i])
    if (tib < 32) {
        float hv  = hour[bld];
        float acc = he_b2[tib];
        #pragma unroll
        for (int k2 = 0; k2 < 16; ++k2) {
            float tt = fmaxf(hv * he_w1[k2] + he_b1[k2], 0.0f);
            acc += tt * he_w2[k2 * 32 + tib];
        }
        inb[560 + tib] = acc;
    }
    __syncthreads();

    // L1: 544 -> 256, each thread computes 4 outputs
    float a1[4];
    {
        const int j0 = tib * 4;
        a1[0] = d_b1[j0]; a1[1] = d_b1[j0 + 1]; a1[2] = d_b1[j0 + 2]; a1[3] = d_b1[j0 + 3];
        const float* zz = inb + 48;
        #pragma unroll 4
        for (int i = 0; i < 544; ++i) {
            float zi = zz[i];
            float4 w = *reinterpret_cast<const float4*>(d_w1 + i * 256 + j0);
            a1[0] += zi * w.x; a1[1] += zi * w.y; a1[2] += zi * w.z; a1[3] += zi * w.w;
        }
        #pragma unroll
        for (int q = 0; q < 4; q++) a1[q] = fmaxf(a1[q], 0.0f);
    }
    __syncthreads();   // all z reads done
    {
        const int j0 = tib * 4;
        inb[j0] = a1[0]; inb[j0 + 1] = a1[1]; inb[j0 + 2] = a1[2]; inb[j0 + 3] = a1[3];
    }
    __syncthreads();

    // L2: 256 -> 128, each thread computes 2 outputs; writes to [256..384)
    {
        const int j0 = tib * 2;
        float a2x = d_b2[j0], a2y = d_b2[j0 + 1];
        #pragma unroll 4
        for (int i = 0; i < 256; ++i) {
            float zi = inb[i];
            float2 w = *reinterpret_cast<const float2*>(d_w2 + i * 128 + j0);
            a2x += zi * w.x; a2y += zi * w.y;
        }
        inb[256 + j0]     = fmaxf(a2x, 0.0f);   // disjoint from read region [0..256)
        inb[256 + j0 + 1] = fmaxf(a2y, 0.0f);
    }
    __syncthreads();

    // L3: 128 -> 30 + sigmoid
    if (tib < 30 && valid) {
        float a3 = d_b3[tib];
        #pragma unroll 4
        for (int i = 0; i < 128; ++i)
            a3 += inb[256 + i] * d_w3[i * 30 + tib];
        out[b * 30 + tib] = sigf(a3);
    }
}

extern "C" void kernel_launch(void* const* d_in, const int* in_sizes, int n_in,
                              void* d_out, int out_size)
{
    const float* x      = (const float*)d_in[0];
    const float* hour   = (const float*)d_in[1];
    const float* conv_w = (const float*)d_in[2];
    const float* conv_b = (const float*)d_in[3];
    const float* he_w1  = (const float*)d_in[4];
    const float* he_b1  = (const float*)d_in[5];
    const float* he_w2  = (const float*)d_in[6];
    const float* he_b2  = (const float*)d_in[7];
    const float* d_w1   = (const float*)d_in[8];
    const float* d_b1   = (const float*)d_in[9];
    const float* d_w2   = (const float*)d_in[10];
    const float* d_b2   = (const float*)d_in[11];
    const float* d_w3   = (const float*)d_in[12];
    const float* d_b3   = (const float*)d_in[13];

    const int B    = in_sizes[0] / 576;          // 12*3*4*4
    const int grid = (B + NB - 1) / NB;
    const size_t sm = (size_t)(WCNT + 128 + NB * INS) * sizeof(float);  // 180,736 B

    cudaFuncSetAttribute(wq_fused_kernel,
                         cudaFuncAttributeMaxDynamicSharedMemorySize, (int)sm);

    wq_fused_kernel<<<grid, NTHR, sm>>>(x, hour, conv_w, conv_b,
                                        he_w1, he_b1, he_w2, he_b2,
                                        d_w1, d_b1, d_w2, d_b2, d_w3, d_b3,
                                        (float*)d_out, B);
}